// round 1
// baseline (speedup 1.0000x reference)
#include <cuda_runtime.h>

// StreamNet 3x3/s1 halo conv, fp32, packed-f32x2 FFMA2 direct conv.
// out[b,co,y,x] = bias[co] + sum_ci sum_{dy,dx} W[co,ci,dy,dx] * I[b,ci,y+dy,x+dx]
// I = vcat(bbuf, hcat(rbuf, x_with_last_col_zeroed))  -> [258,258] padded plane.

using u64 = unsigned long long;

__device__ __forceinline__ u64 pack2(float lo, float hi) {
    u64 r; asm("mov.b64 %0, {%1, %2};" : "=l"(r) : "f"(lo), "f"(hi)); return r;
}
__device__ __forceinline__ void unpack2(u64 v, float& lo, float& hi) {
    asm("mov.b64 {%0, %1}, %2;" : "=f"(lo), "=f"(hi) : "l"(v));
}
// d = a*b + c, elementwise on packed {f32,f32}
__device__ __forceinline__ u64 ffma2(u64 a, u64 b, u64 c) {
    u64 d;
    asm("fma.rn.f32x2 %0, %1, %2, %3;" : "=l"(d) : "l"(a), "l"(b), "l"(c));
    return d;
}
// (hi(a), lo(b)) -- the "odd-aligned" pair between two even pairs
__device__ __forceinline__ u64 mid2(u64 a, u64 b) {
    float alo, ahi, blo, bhi;
    unpack2(a, alo, ahi); unpack2(b, blo, bhi);
    return pack2(ahi, blo);
}

// Tile geometry
#define TW 64          // output tile width
#define TH 4           // output tile height
#define IW 66          // input tile width  (TW + 2)
#define IWP 68         // padded smem row stride (floats), keeps u64 alignment
#define IH 6           // input tile height (TH + 2)
#define NCH 32

// smem: ish = 32*6*68 floats (52224 B), wsh = 32*32*9 u64 (73728 B) => 125952 B
#define ISH_FLOATS (NCH * IH * IWP)
#define WSH_U64    (NCH * NCH * 9)

__global__ __launch_bounds__(256, 1)
void streamnet_conv_kernel(const float* __restrict__ x,
                           const float* __restrict__ rbuf,
                           const float* __restrict__ bbuf,
                           const float* __restrict__ W,
                           const float* __restrict__ bias,
                           float* __restrict__ out)
{
    extern __shared__ float smem[];
    float* ish = smem;                               // [ci][row][IWP]
    u64*   wsh = (u64*)(smem + ISH_FLOATS);          // [ci][co][tap], duplicated

    const int tid = threadIdx.x;
    const int X0 = blockIdx.x * TW;
    const int Y0 = blockIdx.y * TH;
    const int b  = blockIdx.z;

    // ---- stage weights, duplicated into f32x2 pairs ----
    // W is OIHW: linear i = ((co*32+ci)*3+dy)*3+dx
    for (int i = tid; i < NCH * NCH * 9; i += 256) {
        float w = W[i];
        int co  = i / 288;
        int rem = i - co * 288;
        int ci  = rem / 9;
        int tap = rem - ci * 9;
        wsh[(ci * NCH + co) * 9 + tap] = pack2(w, w);
    }

    // ---- stage input tile (halo-resolved) ----
    const int bc0 = b * NCH;
    for (int i = tid; i < NCH * IH * IW; i += 256) {
        int ci  = i / (IH * IW);
        int rem = i - ci * (IH * IW);
        int rr  = rem / IW;
        int cc  = rem - rr * IW;
        int gi  = Y0 + rr;            // padded row  [0,258)
        int gj  = X0 + cc;            // padded col  [0,258)
        int bc  = bc0 + ci;
        float v;
        if (gi < 2) {
            v = bbuf[(bc * 2 + gi) * 258 + gj];
        } else if (gj < 2) {
            v = rbuf[(bc * 256 + (gi - 2)) * 2 + gj];
        } else {
            int xr = gi - 2, xc = gj - 2;
            v = (xc == 255) ? 0.0f : x[(bc * 256 + xr) * 256 + xc];
        }
        ish[(ci * IH + rr) * IWP + cc] = v;
    }
    __syncthreads();

    // thread mapping: tx in [0,8) -> 8 px, cog in [0,8) -> 4 couts, ty in [0,4)
    const int tx  = tid & 7;
    const int cog = (tid >> 3) & 7;
    const int ty  = tid >> 6;
    const int co0 = cog * 4;
    const int colbase = tx * 8;

    u64 acc[4][4];
    #pragma unroll
    for (int cc = 0; cc < 4; cc++) {
        float bv = bias[co0 + cc];
        u64 bb = pack2(bv, bv);
        #pragma unroll
        for (int k = 0; k < 4; k++) acc[cc][k] = bb;
    }

    for (int ci = 0; ci < NCH; ci++) {
        // even-aligned input pairs for the 3 rows this thread touches
        u64 e[3][5];
        #pragma unroll
        for (int dy = 0; dy < 3; dy++) {
            const u64* row = (const u64*)&ish[(ci * IH + ty + dy) * IWP + colbase];
            #pragma unroll
            for (int k = 0; k < 5; k++) e[dy][k] = row[k];
        }
        u64 o[3][4];
        #pragma unroll
        for (int dy = 0; dy < 3; dy++)
            #pragma unroll
            for (int k = 0; k < 4; k++) o[dy][k] = mid2(e[dy][k], e[dy][k + 1]);

        const u64* wp = &wsh[(ci * NCH + co0) * 9];
        #pragma unroll
        for (int cc = 0; cc < 4; cc++) {
            u64 w0 = wp[cc * 9 + 0], w1 = wp[cc * 9 + 1], w2 = wp[cc * 9 + 2];
            u64 w3 = wp[cc * 9 + 3], w4 = wp[cc * 9 + 4], w5 = wp[cc * 9 + 5];
            u64 w6 = wp[cc * 9 + 6], w7 = wp[cc * 9 + 7], w8 = wp[cc * 9 + 8];
            #pragma unroll
            for (int k = 0; k < 4; k++) {
                u64 a = acc[cc][k];
                a = ffma2(e[0][k],     w0, a);
                a = ffma2(o[0][k],     w1, a);
                a = ffma2(e[0][k + 1], w2, a);
                a = ffma2(e[1][k],     w3, a);
                a = ffma2(o[1][k],     w4, a);
                a = ffma2(e[1][k + 1], w5, a);
                a = ffma2(e[2][k],     w6, a);
                a = ffma2(o[2][k],     w7, a);
                a = ffma2(e[2][k + 1], w8, a);
                acc[cc][k] = a;
            }
        }
    }

    // ---- write back (float2 stores, bias already folded in) ----
    const int gy = Y0 + ty;
    #pragma unroll
    for (int cc = 0; cc < 4; cc++) {
        float* orow = &out[((b * NCH + co0 + cc) * 256 + gy) * 256 + X0 + colbase];
        #pragma unroll
        for (int k = 0; k < 4; k++) {
            float lo, hi;
            unpack2(acc[cc][k], lo, hi);
            reinterpret_cast<float2*>(orow)[k] = make_float2(lo, hi);
        }
    }
}

extern "C" void kernel_launch(void* const* d_in, const int* in_sizes, int n_in,
                              void* d_out, int out_size) {
    const float* x    = (const float*)d_in[0];
    const float* rbuf = (const float*)d_in[1];
    const float* bbuf = (const float*)d_in[2];
    const float* W    = (const float*)d_in[3];
    const float* bias = (const float*)d_in[4];
    float* out = (float*)d_out;

    const int smem_bytes = ISH_FLOATS * 4 + WSH_U64 * 8;  // 125952
    cudaFuncSetAttribute(streamnet_conv_kernel,
                         cudaFuncAttributeMaxDynamicSharedMemorySize, smem_bytes);

    dim3 grid(256 / TW, 256 / TH, 8);   // (4, 64, 8)
    streamnet_conv_kernel<<<grid, 256, smem_bytes>>>(x, rbuf, bbuf, W, bias, out);
}

// round 2
// speedup vs baseline: 1.4630x; 1.4630x over previous
#include <cuda_runtime.h>

// StreamNet 3x3/s1 halo conv, fp32, packed-f32x2 FFMA2 direct conv.
// Round 2: warp-uniform co/ci (broadcast LDS.128 weights), 512 thr, 64x8 tile.
// out[b,co,y,x] = bias[co] + sum_ci sum_{dy,dx} W[co,ci,dy,dx] * I[b,ci,y+dy,x+dx]
// I = vcat(bbuf, hcat(rbuf, x_with_last_col_zeroed))  -> [258,258] padded plane.

using u64 = unsigned long long;

__device__ __forceinline__ u64 pack2(float lo, float hi) {
    u64 r; asm("mov.b64 %0, {%1, %2};" : "=l"(r) : "f"(lo), "f"(hi)); return r;
}
__device__ __forceinline__ void unpack2(u64 v, float& lo, float& hi) {
    asm("mov.b64 {%0, %1}, %2;" : "=f"(lo), "=f"(hi) : "l"(v));
}
__device__ __forceinline__ u64 ffma2(u64 a, u64 b, u64 c) {
    u64 d;
    asm("fma.rn.f32x2 %0, %1, %2, %3;" : "=l"(d) : "l"(a), "l"(b), "l"(c));
    return d;
}
// (hi(a), lo(b)) -- odd-aligned pair between two even pairs
__device__ __forceinline__ u64 mid2(u64 a, u64 b) {
    float alo, ahi, blo, bhi;
    unpack2(a, alo, ahi); unpack2(b, blo, bhi);
    return pack2(ahi, blo);
}

#define TW 64           // output tile width (cols)
#define TH 8            // output tile height (rows per CTA)
#define IW 66           // input tile width (floats per row; 33 u64)
#define IH 10           // input tile height (TH + 2)
#define NCH 32

#define ISH_FLOATS (NCH * IH * IW)      // 21120 floats = 84480 B
#define WSH_U64    (NCH * NCH * 10)     // 10240 u64   = 81920 B (taps padded 9->10)

__global__ __launch_bounds__(512, 1)
void streamnet_conv_kernel(const float* __restrict__ x,
                           const float* __restrict__ rbuf,
                           const float* __restrict__ bbuf,
                           const float* __restrict__ W,
                           const float* __restrict__ bias,
                           float* __restrict__ out)
{
    extern __shared__ float smem[];
    float* ish = smem;                              // [ci][row][IW]
    u64*   wsh = (u64*)(smem + ISH_FLOATS);         // [ci][co][10], dup pairs, 80B/co

    const int tid = threadIdx.x;
    const int X0 = blockIdx.x * TW;
    const int Y0 = blockIdx.y * TH;
    const int b  = blockIdx.z;

    // ---- stage weights, duplicated f32x2, padded to 10 u64 per (ci,co) ----
    for (int i = tid; i < NCH * NCH * 9; i += 512) {
        float w = W[i];
        int co  = i / 288;
        int rem = i - co * 288;
        int ci  = rem / 9;
        int tap = rem - ci * 9;
        wsh[(ci * NCH + co) * 10 + tap] = pack2(w, w);
    }

    // ---- stage input tile (halo-resolved) ----
    const int bc0 = b * NCH;
    for (int i = tid; i < NCH * IH * IW; i += 512) {
        int ci  = i / (IH * IW);
        int rem = i - ci * (IH * IW);
        int rr  = rem / IW;
        int cc  = rem - rr * IW;
        int gi  = Y0 + rr;             // padded row [0,258)
        int gj  = X0 + cc;             // padded col [0,258)
        int bc  = bc0 + ci;
        float v;
        if (gi < 2) {
            v = bbuf[(bc * 2 + gi) * 258 + gj];
        } else if (gj < 2) {
            v = rbuf[(bc * 256 + (gi - 2)) * 2 + gj];
        } else {
            int xr = gi - 2, xc = gj - 2;
            v = (xc == 255) ? 0.0f : x[(bc * 256 + xr) * 256 + xc];
        }
        ish[(ci * IH + rr) * IW + cc] = v;
    }
    __syncthreads();

    // warp layout: lane owns output cols (2*lane, 2*lane+1); warp owns 4 co, 4 rows
    const int lane = tid & 31;
    const int wid  = tid >> 5;
    const int co0  = (wid & 7) * 4;      // 8 co-groups x 4 co = 32
    const int row0 = (wid >> 3) * 4;     // 2 row-groups x 4 rows = 8

    u64 acc[4][4];
    #pragma unroll
    for (int co = 0; co < 4; co++) {
        float bv = bias[co0 + co];
        u64 bb = pack2(bv, bv);
        #pragma unroll
        for (int r = 0; r < 4; r++) acc[co][r] = bb;
    }

    for (int ci = 0; ci < NCH; ci++) {
        // input pairs for the 6 rows this warp needs (contiguous LDS.64, 2 wf)
        u64 e[6][2], o[6];
        const u64* base = (const u64*)&ish[(ci * IH + row0) * IW];
        #pragma unroll
        for (int r = 0; r < 6; r++) {
            const u64* row = base + r * (IW / 2);
            e[r][0] = row[lane];
            e[r][1] = row[lane + 1];
            o[r]    = mid2(e[r][0], e[r][1]);
        }

        const u64* wp = &wsh[(ci * NCH + co0) * 10];
        #pragma unroll
        for (int co = 0; co < 4; co++) {
            // warp-uniform broadcast loads: 4x LDS.128 + 1x LDS.64
            const ulonglong2* w2 = (const ulonglong2*)(wp + co * 10);
            ulonglong2 w01 = w2[0];
            ulonglong2 w23 = w2[1];
            ulonglong2 w45 = w2[2];
            ulonglong2 w67 = w2[3];
            u64 w8 = wp[co * 10 + 8];
            #pragma unroll
            for (int r = 0; r < 4; r++) {
                u64 a = acc[co][r];
                a = ffma2(e[r][0],     w01.x, a);
                a = ffma2(o[r],        w01.y, a);
                a = ffma2(e[r][1],     w23.x, a);
                a = ffma2(e[r + 1][0], w23.y, a);
                a = ffma2(o[r + 1],    w45.x, a);
                a = ffma2(e[r + 1][1], w45.y, a);
                a = ffma2(e[r + 2][0], w67.x, a);
                a = ffma2(o[r + 2],    w67.y, a);
                a = ffma2(e[r + 2][1], w8,    a);
                acc[co][r] = a;
            }
        }
    }

    // ---- write back: lane-contiguous float2 stores ----
    #pragma unroll
    for (int co = 0; co < 4; co++) {
        #pragma unroll
        for (int r = 0; r < 4; r++) {
            int gy = Y0 + row0 + r;
            float lo, hi;
            unpack2(acc[co][r], lo, hi);
            float* orow = &out[((b * NCH + co0 + co) * 256 + gy) * 256 + X0];
            reinterpret_cast<float2*>(orow)[lane] = make_float2(lo, hi);
        }
    }
}

extern "C" void kernel_launch(void* const* d_in, const int* in_sizes, int n_in,
                              void* d_out, int out_size) {
    const float* x    = (const float*)d_in[0];
    const float* rbuf = (const float*)d_in[1];
    const float* bbuf = (const float*)d_in[2];
    const float* W    = (const float*)d_in[3];
    const float* bias = (const float*)d_in[4];
    float* out = (float*)d_out;

    const int smem_bytes = ISH_FLOATS * 4 + WSH_U64 * 8;  // 166400
    cudaFuncSetAttribute(streamnet_conv_kernel,
                         cudaFuncAttributeMaxDynamicSharedMemorySize, smem_bytes);

    dim3 grid(256 / TW, 256 / TH, 8);   // (4, 32, 8) = 1024 CTAs
    streamnet_conv_kernel<<<grid, 512, smem_bytes>>>(x, rbuf, bbuf, W, bias, out);
}

// round 3
// speedup vs baseline: 1.7730x; 1.2119x over previous
#include <cuda_runtime.h>

// StreamNet 3x3/s1 halo conv, fp32, FFMA2 with co-packed accumulators.
// Round 3: pack (co, co+1) in f32x2. Weights = natural pairs in smem.
// Inputs = duplicated (v,v) u64 pairs in smem. Mainloop has zero repacking.
// out[b,co,y,x] = bias[co] + sum_ci sum_{dy,dx} W[co,ci,dy,dx] * I[b,ci,y+dy,x+dx]
// I = vcat(bbuf, hcat(rbuf, x_with_last_col_zeroed))  -> [258,258] padded plane.

using u64 = unsigned long long;

__device__ __forceinline__ u64 pack2(float lo, float hi) {
    u64 r; asm("mov.b64 %0, {%1, %2};" : "=l"(r) : "f"(lo), "f"(hi)); return r;
}
__device__ __forceinline__ void unpack2(u64 v, float& lo, float& hi) {
    asm("mov.b64 {%0, %1}, %2;" : "=f"(lo), "=f"(hi) : "l"(v));
}
__device__ __forceinline__ u64 ffma2(u64 a, u64 b, u64 c) {
    u64 d;
    asm("fma.rn.f32x2 %0, %1, %2, %3;" : "=l"(d) : "l"(a), "l"(b), "l"(c));
    return d;
}

#define TW 64            // output tile width (cols)
#define TH 8             // output tile height
#define IW 66            // input tile width (values / u64-dup entries per row)
#define IH 10            // input tile height (TH + 2)
#define NCH 32

#define DSH_U64 (NCH * IH * IW)      // 21120 u64 = 168960 B  (dup input)
#define WSH_U64 (NCH * 16 * 10)      // 5120 u64  = 40960 B   (co-pair weights, pad 9->10)

__global__ __launch_bounds__(512, 1)
void streamnet_conv_kernel(const float* __restrict__ x,
                           const float* __restrict__ rbuf,
                           const float* __restrict__ bbuf,
                           const float* __restrict__ W,
                           const float* __restrict__ bias,
                           float* __restrict__ out)
{
    extern __shared__ u64 smem64[];
    u64* dsh = smem64;                 // [ci][row][col] dup pairs (v,v)
    u64* wsh = smem64 + DSH_U64;       // [ci][cp][10] pairs (W[2cp], W[2cp+1])

    const int tid = threadIdx.x;
    const int X0 = blockIdx.x * TW;
    const int Y0 = blockIdx.y * TH;
    const int b  = blockIdx.z;

    // ---- stage weights as natural (co, co+1) pairs ----
    // W OIHW: W[co][ci][t] at (co*32+ci)*9+t
    for (int i = tid; i < NCH * 16 * 9; i += 512) {
        int ci  = i / 144;
        int rem = i - ci * 144;
        int cp  = rem / 9;
        int t   = rem - cp * 9;
        float w0 = W[((2 * cp)     * NCH + ci) * 9 + t];
        float w1 = W[((2 * cp + 1) * NCH + ci) * 9 + t];
        wsh[(ci * 16 + cp) * 10 + t] = pack2(w0, w1);
    }

    // ---- stage input tile, duplicated (v,v), halo-resolved ----
    const int bc0 = b * NCH;
    for (int i = tid; i < DSH_U64; i += 512) {
        int ci  = i / (IH * IW);
        int rem = i - ci * (IH * IW);
        int rr  = rem / IW;
        int cc  = rem - rr * IW;
        int gi  = Y0 + rr;             // padded row [0,258)
        int gj  = X0 + cc;             // padded col [0,258)
        int bc  = bc0 + ci;
        float v;
        if (gi < 2) {
            v = bbuf[(bc * 2 + gi) * 258 + gj];
        } else if (gj < 2) {
            v = rbuf[(bc * 256 + (gi - 2)) * 2 + gj];
        } else {
            int xr = gi - 2, xc = gj - 2;
            v = (xc == 255) ? 0.0f : x[(bc * 256 + xr) * 256 + xc];
        }
        dsh[i] = pack2(v, v);
    }
    __syncthreads();

    // warp layout: 16 warps = 8 co-groups x 2 row-groups.
    // lane owns output cols (2*lane, 2*lane+1); thread: 4 co (2 pairs) x 4 rows x 2 px.
    const int lane = tid & 31;
    const int wid  = tid >> 5;
    const int cp0  = (wid & 7) * 2;      // co pair base: 8 groups x 2 pairs = 16 pairs
    const int row0 = (wid >> 3) * 4;     // 2 row-groups x 4 rows

    u64 acc[2][4][2];
    #pragma unroll
    for (int cp = 0; cp < 2; cp++) {
        u64 bb = pack2(bias[(cp0 + cp) * 2], bias[(cp0 + cp) * 2 + 1]);
        #pragma unroll
        for (int r = 0; r < 4; r++) { acc[cp][r][0] = bb; acc[cp][r][1] = bb; }
    }

    for (int ci = 0; ci < NCH; ci++) {
        // input dup-pairs: 6 rows x 4 cols, loaded as 2x LDS.128 per row
        const u64* drow = &dsh[(ci * IH + row0) * IW + 2 * lane];
        ulonglong2 p[6][2];
        #pragma unroll
        for (int r = 0; r < 6; r++) {
            p[r][0] = *(const ulonglong2*)(drow + r * IW);
            p[r][1] = *(const ulonglong2*)(drow + r * IW + 2);
        }

        #pragma unroll
        for (int cp = 0; cp < 2; cp++) {
            const u64* wp = &wsh[(ci * 16 + cp0 + cp) * 10];
            ulonglong2 w01 = *(const ulonglong2*)(wp);
            ulonglong2 w23 = *(const ulonglong2*)(wp + 2);
            ulonglong2 w45 = *(const ulonglong2*)(wp + 4);
            ulonglong2 w67 = *(const ulonglong2*)(wp + 6);
            u64 w8 = wp[8];
            #pragma unroll
            for (int r = 0; r < 4; r++) {
                u64 a0 = acc[cp][r][0];   // px x0
                u64 a1 = acc[cp][r][1];   // px x0+1
                a0 = ffma2(p[r][0].x,     w01.x, a0);  a1 = ffma2(p[r][0].y,     w01.x, a1);
                a0 = ffma2(p[r][0].y,     w01.y, a0);  a1 = ffma2(p[r][1].x,     w01.y, a1);
                a0 = ffma2(p[r][1].x,     w23.x, a0);  a1 = ffma2(p[r][1].y,     w23.x, a1);
                a0 = ffma2(p[r + 1][0].x, w23.y, a0);  a1 = ffma2(p[r + 1][0].y, w23.y, a1);
                a0 = ffma2(p[r + 1][0].y, w45.x, a0);  a1 = ffma2(p[r + 1][1].x, w45.x, a1);
                a0 = ffma2(p[r + 1][1].x, w45.y, a0);  a1 = ffma2(p[r + 1][1].y, w45.y, a1);
                a0 = ffma2(p[r + 2][0].x, w67.x, a0);  a1 = ffma2(p[r + 2][0].y, w67.x, a1);
                a0 = ffma2(p[r + 2][0].y, w67.y, a0);  a1 = ffma2(p[r + 2][1].x, w67.y, a1);
                a0 = ffma2(p[r + 2][1].x, w8,    a0);  a1 = ffma2(p[r + 2][1].y, w8,    a1);
                acc[cp][r][0] = a0;
                acc[cp][r][1] = a1;
            }
        }
    }

    // ---- write back: per co-plane coalesced float2 stores ----
    #pragma unroll
    for (int cp = 0; cp < 2; cp++) {
        int coA = (cp0 + cp) * 2;
        #pragma unroll
        for (int r = 0; r < 4; r++) {
            int gy = Y0 + row0 + r;
            float a_lo, a_hi, b_lo, b_hi;
            unpack2(acc[cp][r][0], a_lo, a_hi);   // (coA, coA+1) at x0
            unpack2(acc[cp][r][1], b_lo, b_hi);   // (coA, coA+1) at x0+1
            float* rowA = &out[((b * NCH + coA)     * 256 + gy) * 256 + X0];
            float* rowB = &out[((b * NCH + coA + 1) * 256 + gy) * 256 + X0];
            reinterpret_cast<float2*>(rowA)[lane] = make_float2(a_lo, b_lo);
            reinterpret_cast<float2*>(rowB)[lane] = make_float2(a_hi, b_hi);
        }
    }
}

extern "C" void kernel_launch(void* const* d_in, const int* in_sizes, int n_in,
                              void* d_out, int out_size) {
    const float* x    = (const float*)d_in[0];
    const float* rbuf = (const float*)d_in[1];
    const float* bbuf = (const float*)d_in[2];
    const float* W    = (const float*)d_in[3];
    const float* bias = (const float*)d_in[4];
    float* out = (float*)d_out;

    const int smem_bytes = (DSH_U64 + WSH_U64) * 8;   // 209920
    cudaFuncSetAttribute(streamnet_conv_kernel,
                         cudaFuncAttributeMaxDynamicSharedMemorySize, smem_bytes);

    dim3 grid(256 / TW, 256 / TH, 8);   // (4, 32, 8) = 1024 CTAs
    streamnet_conv_kernel<<<grid, 512, smem_bytes>>>(x, rbuf, bbuf, W, bias, out);
}

// round 5
// speedup vs baseline: 2.0640x; 1.1641x over previous
#include <cuda_runtime.h>
#include <cuda_fp16.h>
#include <cstdint>

// StreamNet 3x3/s1 halo conv via HMMA (mma.sync m16n8k16 f16->f32), W hi/lo split.
// D[co, px] = sum_tap sum_ci (Wh+Wl)[co,ci,tap] * I[ci, px_shifted(tap)]
// I = vcat(bbuf, hcat(rbuf, x with last col zeroed)) -> padded [258,258].

#define APX 80                    // bytes per pixel in A smem (32 ci * 2B + 16 pad)
#define AROW (132 * APX)          // 10560 B per padded row
#define A_BYTES (4 * AROW)        // 42240
#define WOFF A_BYTES
#define WREG 1536                 // one (tap,cihalf,hl) region: 32 co * 48 B
#define W_BYTES (36 * WREG)       // 55296
#define SMEM_TOTAL (A_BYTES + W_BYTES)   // 97536

__device__ __forceinline__ uint32_t smem_u32(const void* p) {
    uint32_t a;
    asm("{ .reg .u64 t; cvta.to.shared.u64 t, %1; cvt.u32.u64 %0, t; }" : "=r"(a) : "l"(p));
    return a;
}
__device__ __forceinline__ void ldmx4(uint32_t* r, uint32_t addr) {
    asm volatile("ldmatrix.sync.aligned.m8n8.x4.shared.b16 {%0,%1,%2,%3}, [%4];"
                 : "=r"(r[0]), "=r"(r[1]), "=r"(r[2]), "=r"(r[3]) : "r"(addr));
}
__device__ __forceinline__ void mma16816(float* d, const uint32_t* a,
                                         uint32_t b0, uint32_t b1) {
    asm volatile(
        "mma.sync.aligned.m16n8k16.row.col.f32.f16.f16.f32 "
        "{%0,%1,%2,%3}, {%4,%5,%6,%7}, {%8,%9}, {%0,%1,%2,%3};"
        : "+f"(d[0]), "+f"(d[1]), "+f"(d[2]), "+f"(d[3])
        : "r"(a[0]), "r"(a[1]), "r"(a[2]), "r"(a[3]), "r"(b0), "r"(b1));
}

__global__ __launch_bounds__(256, 1)
void streamnet_hmma_kernel(const float* __restrict__ x,
                           const float* __restrict__ rbuf,
                           const float* __restrict__ bbuf,
                           const float* __restrict__ W,
                           const float* __restrict__ bias,
                           float* __restrict__ out)
{
    extern __shared__ char smem[];
    const uint32_t sbase = smem_u32(smem);

    const int tid  = threadIdx.x;
    const int lane = tid & 31;
    const int wid  = tid >> 5;
    const int x0   = blockIdx.x * 128;
    const int y    = blockIdx.y * 2;
    const int b    = blockIdx.z;

    // ---- stage raw W (fp32) into A-region scratch, coalesced ----
    {
        float* wraw = (float*)smem;
        for (int i = tid; i < 9216; i += 256) wraw[i] = W[i];
    }
    __syncthreads();

    // ---- build W hi/lo fp16, layout [region = (tap*2+cihalf)*2+hl][co (48B rows)][ci16] ----
    {
        const float* wraw = (const float*)smem;
        for (int i = tid; i < 9216; i += 256) {
            int co  = i / 288;
            int rem = i - co * 288;
            int ci  = rem / 9;
            int tap = rem - ci * 9;
            float w = wraw[i];
            __half h = __float2half_rn(w);
            __half l = __float2half_rn(w - __half2float(h));
            char* p = smem + WOFF + ((tap * 2 + (ci >> 4)) * 2) * WREG + co * 48 + (ci & 15) * 2;
            *(__half*)p = h;
            *(__half*)(p + WREG) = l;
        }
    }
    __syncthreads();

    // ---- stage input tile: [r 0..3][col 0..129][ci], fp16, halo-resolved ----
    for (int i = tid; i < 16640; i += 256) {
        int c  = i % 130;
        int t  = i / 130;
        int r  = t & 3;
        int ci = t >> 2;
        int gi = y + r;            // padded row [0,258)
        int gj = x0 + c;           // padded col [0,258)
        int bc = b * 32 + ci;
        float v;
        if (gi < 2)          v = bbuf[(bc * 2 + gi) * 258 + gj];
        else if (gj < 2)     v = rbuf[(bc * 256 + (gi - 2)) * 2 + gj];
        else if (gj == 257)  v = 0.0f;
        else                 v = x[(bc * 256 + (gi - 2)) * 256 + (gj - 2)];
        *(__half*)(smem + (r * 132 + c) * APX + ci * 2) = __float2half_rn(v);
    }
    __syncthreads();

    // ---- mainloop: warp = 32 co x 32 px; wid>>2 selects row, wid&3 col-base ----
    const int rw = wid >> 2;          // output row within pair
    const int cb = (wid & 3) * 32;    // px base

    float acc[2][4][4];
    #pragma unroll
    for (int mt = 0; mt < 2; mt++)
        #pragma unroll
        for (int nt = 0; nt < 4; nt++)
            #pragma unroll
            for (int j = 0; j < 4; j++) acc[mt][nt][j] = 0.0f;

    // W ldmatrix lane address: rows = co (16 rows per matrix-pair), 48B stride
    const uint32_t wl_base = sbase + WOFF + (lane & 15) * 48 + (lane >> 4) * 16;
    // B fragment lane base: n = px (lane>>2), k = ci pair (lane&3)
    const char* ab_base = smem + (cb + (lane >> 2)) * APX + (lane & 3) * 4;

    #pragma unroll
    for (int h = 0; h < 2; h++) {
        #pragma unroll
        for (int tap = 0; tap < 9; tap++) {
            const int dy = tap / 3, dx = tap - dy * 3;
            const int regbase = (tap * 2 + h) * 2;

            uint32_t wf[2][2][4];        // [mt co-half][hl]
            #pragma unroll
            for (int mt = 0; mt < 2; mt++)
                #pragma unroll
                for (int hl = 0; hl < 2; hl++)
                    ldmx4(wf[mt][hl], wl_base + (regbase + hl) * WREG + mt * 768);

            const char* arow = ab_base + (rw + dy) * AROW + dx * APX + h * 32;
            #pragma unroll
            for (int nt = 0; nt < 4; nt++) {
                const char* p = arow + nt * 8 * APX;
                uint32_t b0 = *(const uint32_t*)p;
                uint32_t b1 = *(const uint32_t*)(p + 16);
                mma16816(acc[0][nt], wf[0][0], b0, b1);
                mma16816(acc[0][nt], wf[0][1], b0, b1);
                mma16816(acc[1][nt], wf[1][0], b0, b1);
                mma16816(acc[1][nt], wf[1][1], b0, b1);
            }
        }
    }

    // ---- epilogue: d0,d1 = adjacent px -> float2 stores; bias in fp32 ----
    const int oy = y + rw;
    #pragma unroll
    for (int mt = 0; mt < 2; mt++) {
        const int co = mt * 16 + (lane >> 2);
        const float bv0 = bias[co];
        const float bv1 = bias[co + 8];
        #pragma unroll
        for (int nt = 0; nt < 4; nt++) {
            const int px = x0 + cb + nt * 8 + 2 * (lane & 3);
            float* p0 = &out[(((size_t)b * 32 + co) * 256 + oy) * 256 + px];
            float* p1 = p0 + 8 * 65536;   // co + 8 plane
            *(float2*)p0 = make_float2(acc[mt][nt][0] + bv0, acc[mt][nt][1] + bv0);
            *(float2*)p1 = make_float2(acc[mt][nt][2] + bv1, acc[mt][nt][3] + bv1);
        }
    }
}

extern "C" void kernel_launch(void* const* d_in, const int* in_sizes, int n_in,
                              void* d_out, int out_size) {
    const float* x    = (const float*)d_in[0];
    const float* rbuf = (const float*)d_in[1];
    const float* bbuf = (const float*)d_in[2];
    const float* W    = (const float*)d_in[3];
    const float* bias = (const float*)d_in[4];
    float* out = (float*)d_out;

    cudaFuncSetAttribute(streamnet_hmma_kernel,
                         cudaFuncAttributeMaxDynamicSharedMemorySize, SMEM_TOTAL);

    dim3 grid(2, 128, 8);   // col-halves x row-pairs x batch = 2048 CTAs
    streamnet_hmma_kernel<<<grid, 256, SMEM_TOTAL>>>(x, rbuf, bbuf, W, bias, out);
}

// round 6
// speedup vs baseline: 4.8674x; 2.3582x over previous
#include <cuda_runtime.h>
#include <cuda_fp16.h>
#include <cstdint>

// StreamNet 3x3/s1 halo conv via HMMA (mma.sync m16n8k16 f16->f32), single fp16 pass.
// D[co, px] = sum_tap sum_ci W[co,ci,tap] * I[ci, px_shifted(tap)]
// I = vcat(bbuf, hcat(rbuf, x with last col zeroed)) -> padded [258,258].
// A smem: [r(4)][cipair(16)][col(136 pad)] half2  -> conflict-free staging & B loads.
// W smem: 18 regions (tap x kh), 32 co rows x 16 ci fp16, 48B row stride (ldmatrix).

#define ACOL 136
#define PROW (ACOL * 4)             // 544 B per (r, cipair) row
#define A_BYTES (4 * 16 * PROW)     // 34816
#define WOFF A_BYTES
#define WREG 1536                   // 32 co * 48 B
#define W_BYTES (18 * WREG)         // 27648
#define SMEM_TOTAL (A_BYTES + W_BYTES)   // 62464

__device__ __forceinline__ uint32_t smem_u32(const void* p) {
    uint32_t a;
    asm("{ .reg .u64 t; cvta.to.shared.u64 t, %1; cvt.u32.u64 %0, t; }" : "=r"(a) : "l"(p));
    return a;
}
__device__ __forceinline__ void ldmx4(uint32_t* r, uint32_t addr) {
    asm volatile("ldmatrix.sync.aligned.m8n8.x4.shared.b16 {%0,%1,%2,%3}, [%4];"
                 : "=r"(r[0]), "=r"(r[1]), "=r"(r[2]), "=r"(r[3]) : "r"(addr));
}
__device__ __forceinline__ void mma16816(float* d, const uint32_t* a,
                                         uint32_t b0, uint32_t b1) {
    asm volatile(
        "mma.sync.aligned.m16n8k16.row.col.f32.f16.f16.f32 "
        "{%0,%1,%2,%3}, {%4,%5,%6,%7}, {%8,%9}, {%0,%1,%2,%3};"
        : "+f"(d[0]), "+f"(d[1]), "+f"(d[2]), "+f"(d[3])
        : "r"(a[0]), "r"(a[1]), "r"(a[2]), "r"(a[3]), "r"(b0), "r"(b1));
}

// load the (ci, ci+1) pair at padded coords (gi, gj); ci = 2*p
__device__ __forceinline__ __half2 load_pair(const float* __restrict__ x,
                                             const float* __restrict__ rbuf,
                                             const float* __restrict__ bbuf,
                                             int b, int p, int gi, int gj) {
    const int ci = 2 * p;
    const int bc = b * 32 + ci;
    float v0, v1;
    if (gi >= 2 && gj >= 2 && gj != 257) {
        const float* s = x + ((size_t)bc * 256 + (gi - 2)) * 256 + (gj - 2);
        v0 = s[0];
        v1 = s[65536];
    } else if (gi < 2) {
        const float* s = bbuf + ((size_t)bc * 2 + gi) * 258 + gj;
        v0 = s[0];
        v1 = s[2 * 258];
    } else if (gj < 2) {
        const float* s = rbuf + ((size_t)bc * 256 + (gi - 2)) * 2 + gj;
        v0 = s[0];
        v1 = s[512];
    } else {           // gj == 257 -> zeroed image column
        v0 = 0.0f; v1 = 0.0f;
    }
    return __floats2half2_rn(v0, v1);
}

__global__ __launch_bounds__(256, 3)
void streamnet_hmma_kernel(const float* __restrict__ x,
                           const float* __restrict__ rbuf,
                           const float* __restrict__ bbuf,
                           const float* __restrict__ W,
                           const float* __restrict__ bias,
                           float* __restrict__ out)
{
    extern __shared__ char smem[];
    const uint32_t sbase = smem_u32(smem);

    const int tid  = threadIdx.x;
    const int lane = tid & 31;
    const int wid  = tid >> 5;
    const int x0   = blockIdx.x * 128;
    const int y    = blockIdx.y * 2;
    const int b    = blockIdx.z;

    // ---- stage W fp16: region (tap*2+kh), co rows (48B), ci&15 cols ----
    for (int i = tid; i < 9216; i += 256) {
        float w = W[i];                 // coalesced: i = (co*32+ci)*9+tap
        int co  = i / 288;
        int rem = i - co * 288;
        int ci  = rem / 9;
        int tap = rem - ci * 9;
        *(__half*)(smem + WOFF + (tap * 2 + (ci >> 4)) * WREG + co * 48 + (ci & 15) * 2)
            = __float2half_rn(w);
    }

    // ---- stage input: A[r][p][col] half2, conflict-free STS.32 ----
    __half2* A2 = (__half2*)smem;
    for (int t = wid; t < 256; t += 8) {
        const int p  = t & 15;
        const int cg = (t >> 4) & 3;
        const int r  = t >> 6;
        const int c  = cg * 32 + lane;
        A2[(r * 16 + p) * ACOL + c] = load_pair(x, rbuf, bbuf, b, p, y + r, x0 + c);
    }
    if (tid < 128) {   // tail cols 128,129
        const int c = 128 + (tid & 1);
        const int p = (tid >> 1) & 15;
        const int r = (tid >> 5) & 3;
        A2[(r * 16 + p) * ACOL + c] = load_pair(x, rbuf, bbuf, b, p, y + r, x0 + c);
    }
    __syncthreads();

    // ---- mainloop: warp = 32 co x 32 px; rw = row, cb = px base ----
    const int rw = wid >> 2;
    const int cb = (wid & 3) * 32;

    float acc[2][4][4];
    #pragma unroll
    for (int mt = 0; mt < 2; mt++)
        #pragma unroll
        for (int nt = 0; nt < 4; nt++)
            #pragma unroll
            for (int j = 0; j < 4; j++) acc[mt][nt][j] = 0.0f;

    const uint32_t wbase = sbase + WOFF + (lane & 15) * 48 + (lane >> 4) * 16;
    const char* abase = smem + (lane & 3) * PROW + (cb + (lane >> 2)) * 4;

    #pragma unroll
    for (int tap = 0; tap < 9; tap++) {
        const int dy = tap / 3, dx = tap - dy * 3;
        #pragma unroll
        for (int kh = 0; kh < 2; kh++) {
            uint32_t wf0[4], wf1[4];
            ldmx4(wf0, wbase + (tap * 2 + kh) * WREG);
            ldmx4(wf1, wbase + (tap * 2 + kh) * WREG + 768);
            const char* pb = abase + ((rw + dy) * 16 + kh * 8) * PROW + dx * 4;
            #pragma unroll
            for (int nt = 0; nt < 4; nt++) {
                uint32_t b0 = *(const uint32_t*)(pb + nt * 32);
                uint32_t b1 = *(const uint32_t*)(pb + nt * 32 + 4 * PROW);
                mma16816(acc[0][nt], wf0, b0, b1);
                mma16816(acc[1][nt], wf1, b0, b1);
            }
        }
    }

    // ---- epilogue: d0,d1 adjacent px -> float2; d2,d3 = co+8 plane ----
    const int oy = y + rw;
    #pragma unroll
    for (int mt = 0; mt < 2; mt++) {
        const int co = mt * 16 + (lane >> 2);
        const float bv0 = bias[co];
        const float bv1 = bias[co + 8];
        #pragma unroll
        for (int nt = 0; nt < 4; nt++) {
            const int px = x0 + cb + nt * 8 + 2 * (lane & 3);
            float* p0 = &out[(((size_t)b * 32 + co) * 256 + oy) * 256 + px];
            float* p1 = p0 + 8 * 65536;
            *(float2*)p0 = make_float2(acc[mt][nt][0] + bv0, acc[mt][nt][1] + bv0);
            *(float2*)p1 = make_float2(acc[mt][nt][2] + bv1, acc[mt][nt][3] + bv1);
        }
    }
}

extern "C" void kernel_launch(void* const* d_in, const int* in_sizes, int n_in,
                              void* d_out, int out_size) {
    const float* x    = (const float*)d_in[0];
    const float* rbuf = (const float*)d_in[1];
    const float* bbuf = (const float*)d_in[2];
    const float* W    = (const float*)d_in[3];
    const float* bias = (const float*)d_in[4];
    float* out = (float*)d_out;

    cudaFuncSetAttribute(streamnet_hmma_kernel,
                         cudaFuncAttributeMaxDynamicSharedMemorySize, SMEM_TOTAL);

    dim3 grid(2, 128, 8);   // col-halves x row-pairs x batch = 2048 CTAs
    streamnet_hmma_kernel<<<grid, 256, SMEM_TOTAL>>>(x, rbuf, bbuf, W, bias, out);
}

// round 7
// speedup vs baseline: 8.8177x; 1.8116x over previous
#include <cuda_runtime.h>
#include <cuda_fp16.h>
#include <cstdint>

// StreamNet 3x3/s1 halo conv via HMMA (mma.sync m16n8k16 f16->f32), single fp16 pass.
// Round 7: TH=4 rows/CTA, vectorized LDG.128/STS.128 staging, A layout col-shifted +2.
// A smem: [r(6)][cipair(16)][Acol(136)] half2; data in Acols 2..131 (padded col t -> Acol t+2).
// W smem: 18 regions (tap x kh), 32 co rows x 16 ci fp16, 48B stride (ldmatrix).

#define ACOL 136
#define PROW (ACOL * 4)             // 544 B per (r, cipair) row
#define A_BYTES (6 * 16 * PROW)     // 52224
#define WOFF A_BYTES
#define WREG 1536                   // 32 co * 48 B
#define W_BYTES (18 * WREG)         // 27648
#define SMEM_TOTAL (A_BYTES + W_BYTES)   // 79872

__device__ __forceinline__ uint32_t smem_u32(const void* p) {
    uint32_t a;
    asm("{ .reg .u64 t; cvta.to.shared.u64 t, %1; cvt.u32.u64 %0, t; }" : "=r"(a) : "l"(p));
    return a;
}
__device__ __forceinline__ void ldmx4(uint32_t* r, uint32_t addr) {
    asm volatile("ldmatrix.sync.aligned.m8n8.x4.shared.b16 {%0,%1,%2,%3}, [%4];"
                 : "=r"(r[0]), "=r"(r[1]), "=r"(r[2]), "=r"(r[3]) : "r"(addr));
}
__device__ __forceinline__ void mma16816(float* d, const uint32_t* a,
                                         uint32_t b0, uint32_t b1) {
    asm volatile(
        "mma.sync.aligned.m16n8k16.row.col.f32.f16.f16.f32 "
        "{%0,%1,%2,%3}, {%4,%5,%6,%7}, {%8,%9}, {%0,%1,%2,%3};"
        : "+f"(d[0]), "+f"(d[1]), "+f"(d[2]), "+f"(d[3])
        : "r"(a[0]), "r"(a[1]), "r"(a[2]), "r"(a[3]), "r"(b0), "r"(b1));
}
__device__ __forceinline__ uint32_t h2b(__half2 h) {
    return *reinterpret_cast<uint32_t*>(&h);
}

__global__ __launch_bounds__(256, 2)
void streamnet_hmma_kernel(const float* __restrict__ x,
                           const float* __restrict__ rbuf,
                           const float* __restrict__ bbuf,
                           const float* __restrict__ W,
                           const float* __restrict__ bias,
                           float* __restrict__ out)
{
    extern __shared__ char smem[];
    const uint32_t sbase = smem_u32(smem);
    __half2* A2 = (__half2*)smem;

    const int tid  = threadIdx.x;
    const int lane = tid & 31;
    const int wid  = tid >> 5;
    const int x0   = blockIdx.x * 128;
    const int y    = blockIdx.y * 4;
    const int b    = blockIdx.z;

    // ---- stage W fp16: region (tap*2+kh), co rows (48B), ci&15 cols ----
    for (int i = tid; i < 9216; i += 256) {
        float w = W[i];                 // i = (co*32+ci)*9+tap, coalesced
        int co  = i / 288;
        int rem = i - co * 288;
        int ci  = rem / 9;
        int tap = rem - ci * 9;
        *(__half*)(smem + WOFF + (tap * 2 + (ci >> 4)) * WREG + co * 48 + (ci & 15) * 2)
            = __float2half_rn(w);
    }

    // ---- stage input body: tasks (r, p, k) -> padded cols x0+2+4k..+3, Acol 4+4k ----
    for (int t = tid; t < 3072; t += 256) {
        const int k = t & 31;
        const int p = (t >> 5) & 15;
        const int r = t >> 9;
        const int gi = y + r;                 // padded row
        const int bc = b * 32 + 2 * p;
        float4 a, c;
        if (gi >= 2) {
            const float* s = x + ((size_t)bc * 256 + (gi - 2)) * 256 + x0 + 4 * k;
            a = *(const float4*)s;
            c = *(const float4*)(s + 65536);
            if (x0 == 128 && k == 31) { a.w = 0.0f; c.w = 0.0f; }   // padded col 257
        } else {
            const float* s = bbuf + ((size_t)bc * 2 + gi) * 258 + x0 + 2 + 4 * k;
            float2 l0 = *(const float2*)s,        h0 = *(const float2*)(s + 2);
            float2 l1 = *(const float2*)(s + 516), h1 = *(const float2*)(s + 518);
            a = make_float4(l0.x, l0.y, h0.x, h0.y);
            c = make_float4(l1.x, l1.y, h1.x, h1.y);
        }
        uint4 st = make_uint4(h2b(__floats2half2_rn(a.x, c.x)),
                              h2b(__floats2half2_rn(a.y, c.y)),
                              h2b(__floats2half2_rn(a.z, c.z)),
                              h2b(__floats2half2_rn(a.w, c.w)));
        *(uint4*)&A2[(r * 16 + p) * ACOL + 4 + 4 * k] = st;
    }
    // ---- stage head cols (padded x0+0, x0+1 -> Acol 2,3) ----
    if (tid < 96) {
        const int p = tid & 15;
        const int r = tid >> 4;
        const int gi = y + r;
        const int bc = b * 32 + 2 * p;
        float2 a, c;
        if (gi < 2) {
            const float* s = bbuf + ((size_t)bc * 2 + gi) * 258 + x0;
            a = *(const float2*)s;
            c = *(const float2*)(s + 516);
        } else if (x0 == 0) {
            const float* s = rbuf + ((size_t)bc * 256 + (gi - 2)) * 2;
            a = *(const float2*)s;
            c = *(const float2*)(s + 512);
        } else {
            const float* s = x + ((size_t)bc * 256 + (gi - 2)) * 256 + 126;
            a = *(const float2*)s;
            c = *(const float2*)(s + 65536);
        }
        uint2 st = make_uint2(h2b(__floats2half2_rn(a.x, c.x)),
                              h2b(__floats2half2_rn(a.y, c.y)));
        *(uint2*)&A2[(r * 16 + p) * ACOL + 2] = st;
    }
    __syncthreads();

    // ---- mainloop: warp = 32 co x 32 px x 2 rows ----
    const int rw2 = wid >> 2;          // row-pair: output rows {2rw2, 2rw2+1}
    const int cb  = (wid & 3) * 32;    // px base

    float acc[2][2][4][4];             // [row][mt][nt][4]
    #pragma unroll
    for (int r = 0; r < 2; r++)
        #pragma unroll
        for (int mt = 0; mt < 2; mt++)
            #pragma unroll
            for (int nt = 0; nt < 4; nt++)
                #pragma unroll
                for (int j = 0; j < 4; j++) acc[r][mt][nt][j] = 0.0f;

    const uint32_t wbase = sbase + WOFF + (lane & 15) * 48 + (lane >> 4) * 16;
    const char* abase = smem + (lane & 3) * PROW + (cb + (lane >> 2) + 2) * 4;

    #pragma unroll
    for (int tap = 0; tap < 9; tap++) {
        const int dy = tap / 3, dx = tap - dy * 3;
        #pragma unroll
        for (int kh = 0; kh < 2; kh++) {
            uint32_t wf0[4], wf1[4];
            ldmx4(wf0, wbase + (tap * 2 + kh) * WREG);
            ldmx4(wf1, wbase + (tap * 2 + kh) * WREG + 768);
            #pragma unroll
            for (int row = 0; row < 2; row++) {
                const char* pb = abase +
                    ((2 * rw2 + row + dy) * 16 + kh * 8) * PROW + dx * 4;
                #pragma unroll
                for (int nt = 0; nt < 4; nt++) {
                    uint32_t b0 = *(const uint32_t*)(pb + nt * 32);
                    uint32_t b1 = *(const uint32_t*)(pb + nt * 32 + 4 * PROW);
                    mma16816(acc[row][0][nt], wf0, b0, b1);
                    mma16816(acc[row][1][nt], wf1, b0, b1);
                }
            }
        }
    }

    // ---- epilogue: d0,d1 adjacent px -> float2; d2,d3 = co+8 plane ----
    #pragma unroll
    for (int row = 0; row < 2; row++) {
        const int oy = y + 2 * rw2 + row;
        #pragma unroll
        for (int mt = 0; mt < 2; mt++) {
            const int co = mt * 16 + (lane >> 2);
            const float bv0 = bias[co];
            const float bv1 = bias[co + 8];
            #pragma unroll
            for (int nt = 0; nt < 4; nt++) {
                const int px = x0 + cb + nt * 8 + 2 * (lane & 3);
                float* p0 = &out[(((size_t)b * 32 + co) * 256 + oy) * 256 + px];
                float* p1 = p0 + 8 * 65536;
                *(float2*)p0 = make_float2(acc[row][mt][nt][0] + bv0,
                                           acc[row][mt][nt][1] + bv0);
                *(float2*)p1 = make_float2(acc[row][mt][nt][2] + bv1,
                                           acc[row][mt][nt][3] + bv1);
            }
        }
    }
}

extern "C" void kernel_launch(void* const* d_in, const int* in_sizes, int n_in,
                              void* d_out, int out_size) {
    const float* x    = (const float*)d_in[0];
    const float* rbuf = (const float*)d_in[1];
    const float* bbuf = (const float*)d_in[2];
    const float* W    = (const float*)d_in[3];
    const float* bias = (const float*)d_in[4];
    float* out = (float*)d_out;

    cudaFuncSetAttribute(streamnet_hmma_kernel,
                         cudaFuncAttributeMaxDynamicSharedMemorySize, SMEM_TOTAL);

    dim3 grid(2, 64, 8);   // col-halves x row-quads x batch = 1024 CTAs
    streamnet_hmma_kernel<<<grid, 256, SMEM_TOTAL>>>(x, rbuf, bbuf, W, bias, out);
}